// round 4
// baseline (speedup 1.0000x reference)
#include <cuda_runtime.h>
#include <cuda_bf16.h>
#include <cstdint>

// Problem constants
#define L_COMP 16384
#define D      1024
#define D4     (D/4)          // 256 float4 per row
#define L_FULL 32768
#define EPS    1e-4f

// Chunking: small chunks -> big grid -> high occupancy / MLP
#define C   16                // chunk length along L
#define NC  1024              // L_COMP / C
#define TPB 256               // one thread = 4 channels (float4)

// Scratch (device globals: no allocation allowed)
__device__ float g_S[NC * D];        // chunk aggregates (scan-from-zero endpoint)
__device__ float g_P[NC];            // chunk decay products (prod of (1-p))
__device__ float g_Zc[NC * D];       // carry-in (exclusive prefix state) per chunk
__device__ int   g_pos[L_COMP + 1];  // segment start positions in full sequence

__device__ __forceinline__ float clipp(float v) {
    return fminf(fmaxf(v, EPS), 1.0f - EPS);
}

// ---------------------------------------------------------------------------
// Pass 1: per-chunk local scan from zero -> endpoint aggregate S[c][d]
// also writes the chunk decay product g_P[c].
// grid = NC blocks, TPB threads, each thread owns 4 channels (float4)
// ---------------------------------------------------------------------------
__global__ void __launch_bounds__(TPB) pass1_kernel(const float* __restrict__ x,
                                                    const float* __restrict__ p) {
    const int c   = blockIdx.x;
    const int tid = threadIdx.x;

    __shared__ float psm[C];
    __shared__ float adm[C];
    if (tid < C) {
        float pv = clipp(p[c * C + tid]);
        psm[tid] = pv;
        adm[tid] = 1.0f - pv;
    }
    __syncthreads();

    if (tid == 0) {
        float prod = 1.0f;
#pragma unroll
        for (int l = 0; l < C; l++) prod *= adm[l];
        g_P[c] = prod;
    }

    const float4* __restrict__ x4 = (const float4*)x;
    float4 s = make_float4(0.f, 0.f, 0.f, 0.f);
    const int base = c * C;

#pragma unroll
    for (int l = 0; l < C; l++) {
        float4 xv = x4[(base + l) * D4 + tid];
        float a = adm[l], pv = psm[l];
        s.x = fmaf(a, s.x, pv * xv.x);
        s.y = fmaf(a, s.y, pv * xv.y);
        s.z = fmaf(a, s.z, pv * xv.z);
        s.w = fmaf(a, s.w, pv * xv.w);
    }
    ((float4*)g_S)[c * D4 + tid] = s;
}

// ---------------------------------------------------------------------------
// Boundary kernel: block-wide scan of b (L_FULL ints) -> segment starts g_pos
// single block of 1024 threads, int4-vectorized (32 elems / thread)
// ---------------------------------------------------------------------------
__global__ void __launch_bounds__(1024) boundary_kernel(const int* __restrict__ b) {
    const int tid  = threadIdx.x;
    const int lane = tid & 31;
    const int wid  = tid >> 5;
    const int base = tid * 32;

    int4 v8[8];
    const int4* __restrict__ b4 = (const int4*)b;
#pragma unroll
    for (int i = 0; i < 8; i++) v8[i] = b4[tid * 8 + i];

    int cnt = 0;
#pragma unroll
    for (int i = 0; i < 8; i++) cnt += v8[i].x + v8[i].y + v8[i].z + v8[i].w;

    // inclusive warp scan of per-thread counts
    int v = cnt;
#pragma unroll
    for (int o = 1; o < 32; o <<= 1) {
        int n = __shfl_up_sync(0xffffffffu, v, o);
        if (lane >= o) v += n;
    }
    __shared__ int ws[32];
    if (lane == 31) ws[wid] = v;
    __syncthreads();
    if (wid == 0) {
        int w = ws[lane];
#pragma unroll
        for (int o = 1; o < 32; o <<= 1) {
            int n = __shfl_up_sync(0xffffffffu, w, o);
            if (lane >= o) w += n;
        }
        ws[lane] = w;
    }
    __syncthreads();

    int run = v - cnt + (wid > 0 ? ws[wid - 1] : 0);   // exclusive prefix

#pragma unroll
    for (int i = 0; i < 8; i++) {
        if (v8[i].x) g_pos[run++] = base + i * 4 + 0;
        if (v8[i].y) g_pos[run++] = base + i * 4 + 1;
        if (v8[i].z) g_pos[run++] = base + i * 4 + 2;
        if (v8[i].w) g_pos[run++] = base + i * 4 + 3;
    }
    if (tid == 0) g_pos[L_COMP] = L_FULL;
}

// ---------------------------------------------------------------------------
// Pass 2: cross-chunk serial recurrence -> per-chunk carry-ins g_Zc
// grid = 32 blocks x 32 threads; block bb owns channels [bb*32, bb*32+32)
// chain is 1024 dependent FMAs (~4k cycles) — latency-trivial; the point is
// spreading the 8MB of S/Zc traffic across 32 SMs with coalesced 128B lines.
// ---------------------------------------------------------------------------
__global__ void __launch_bounds__(32) pass2_kernel() {
    const int ch = blockIdx.x * 32 + threadIdx.x;   // channel

    __shared__ float Psm[NC];
    for (int i = threadIdx.x; i < NC; i += 32) Psm[i] = g_P[i];
    __syncthreads();

    float z = 0.0f;
#pragma unroll 8
    for (int c = 0; c < NC; c++) {
        g_Zc[c * D + ch] = z;                 // exclusive carry-in
        z = fmaf(Psm[c], z, g_S[c * D + ch]);
    }
}

// ---------------------------------------------------------------------------
// Pass 3: per-chunk scan seeded by carry-in; fused segment-replicated store
// grid = NC blocks, TPB threads, float4 per thread
// ---------------------------------------------------------------------------
__global__ void __launch_bounds__(TPB) pass3_kernel(const float* __restrict__ x,
                                                    const float* __restrict__ p,
                                                    float* __restrict__ out) {
    const int c   = blockIdx.x;
    const int tid = threadIdx.x;

    __shared__ float psm[C];
    __shared__ float adm[C];
    __shared__ int   possm[C + 1];
    if (tid < C) {
        float pv = clipp(p[c * C + tid]);
        psm[tid] = pv;
        adm[tid] = 1.0f - pv;
    }
    if (tid < C + 1) possm[tid] = g_pos[c * C + tid];
    __syncthreads();

    const float4* __restrict__ x4   = (const float4*)x;
    float4* __restrict__       out4 = (float4*)out;

    float4 z = ((const float4*)g_Zc)[c * D4 + tid];
    const int base = c * C;

#pragma unroll
    for (int l = 0; l < C; l++) {
        float4 xv = x4[(base + l) * D4 + tid];
        float a = adm[l], pv = psm[l];
        z.x = fmaf(a, z.x, pv * xv.x);
        z.y = fmaf(a, z.y, pv * xv.y);
        z.z = fmaf(a, z.z, pv * xv.z);
        z.w = fmaf(a, z.w, pv * xv.w);

        int s = possm[l];
        int e = possm[l + 1];
        for (int f = s; f < e; f++)
            out4[f * D4 + tid] = z;
    }
}

// ---------------------------------------------------------------------------
extern "C" void kernel_launch(void* const* d_in, const int* in_sizes, int n_in,
                              void* d_out, int out_size) {
    const float* x = (const float*)d_in[0];   // (1, L_COMP, D) f32
    const float* p = (const float*)d_in[1];   // (L_COMP,)      f32
    const int*   b = (const int*)d_in[2];     // (1, L_FULL)    i32
    float*       o = (float*)d_out;           // (1, L_FULL, D) f32

    pass1_kernel<<<NC, TPB>>>(x, p);
    boundary_kernel<<<1, 1024>>>(b);
    pass2_kernel<<<32, 32>>>();
    pass3_kernel<<<NC, TPB>>>(x, p, o);
}